// round 2
// baseline (speedup 1.0000x reference)
#include <cuda_runtime.h>

// Problem constants (fixed by the reference).
#define BB 2
#define TT 2048
#define CC 1024
#define NH 16
#define HS 64

// Scratch (allocation-free rule: __device__ globals).
// g_S: attention scores / probabilities, [B, NH, T, T]  = 512 MB
// g_Z: per-head projected values  Z[h, b*T + s, c] = x[b] @ W_h, [NH, B*T, C] = 256 MB
__device__ float g_S[134217728];  // 2*16*2048*2048
__device__ float g_Z[67108864];   // 16*2*2048*1024

// ---------------------------------------------------------------------------
// Shared micro-kernel: 128x128 block tile, 256 threads, 8x8 per-thread tile.
// Warp layout: 8 warps as 4 (rows) x 2 (cols); warp tile 32x64.
// Lane layout: ar = (lane>>3)*4 row offset, bc = (lane&7)*4 col offset.
// Thread owns rows {wr+ar+0..3, wr+ar+16..19}, cols {wc+bc+0..3, wc+bc+32..35}
// -> all smem fragment loads are conflict-free / broadcast float4.
// ---------------------------------------------------------------------------
__device__ __forceinline__ void mma_step(const float (*Ash)[128],
                                         const float (*Bsh)[128],
                                         int wr, int wc, int ar, int bc,
                                         float acc[8][8]) {
#pragma unroll
    for (int k = 0; k < 8; ++k) {
        float4 a0 = *(const float4*)&Ash[k][wr + ar];
        float4 a1 = *(const float4*)&Ash[k][wr + 16 + ar];
        float4 b0 = *(const float4*)&Bsh[k][wc + bc];
        float4 b1 = *(const float4*)&Bsh[k][wc + 32 + bc];
        float av[8] = {a0.x, a0.y, a0.z, a0.w, a1.x, a1.y, a1.z, a1.w};
        float bv[8] = {b0.x, b0.y, b0.z, b0.w, b1.x, b1.y, b1.z, b1.w};
#pragma unroll
        for (int i = 0; i < 8; ++i)
#pragma unroll
            for (int j = 0; j < 8; ++j)
                acc[i][j] = fmaf(av[i], bv[j], acc[i][j]);
    }
}

// ---------------------------------------------------------------------------
// Kernel 1: scores  S[b,h,t,s] = (y_t . y_s) / 8   (NT GEMM, K = 64)
// y[b,t,h,:] = x[b, t, h*64 : (h+1)*64]
// ---------------------------------------------------------------------------
__global__ __launch_bounds__(256, 2) void scores_kernel(const float* __restrict__ x) {
    const int bh   = blockIdx.z;            // b*16 + h
    const int b    = bh >> 4;
    const int h    = bh & 15;
    const int row0 = blockIdx.y * 128;      // t tile
    const int col0 = blockIdx.x * 128;      // s tile

    const float* Ab = x + ((size_t)(b * TT + row0)) * CC + h * HS;
    const float* Bb = x + ((size_t)(b * TT + col0)) * CC + h * HS;

    __shared__ float As[2][8][128];
    __shared__ float Bs[2][8][128];

    const int tid  = threadIdx.x;
    const int ldr  = tid >> 1;              // 0..127 (tile row)
    const int ldk  = (tid & 1) * 4;         // 0 or 4 (k offset)
    const int warp = tid >> 5, lane = tid & 31;
    const int wr = (warp & 3) * 32, wc = (warp >> 2) * 64;
    const int ar = (lane >> 3) * 4, bc = (lane & 7) * 4;

    float acc[8][8];
#pragma unroll
    for (int i = 0; i < 8; ++i)
#pragma unroll
        for (int j = 0; j < 8; ++j) acc[i][j] = 0.f;

    // prologue: k-tile 0
    {
        float4 a4 = *(const float4*)(Ab + (size_t)ldr * CC + ldk);
        float4 b4 = *(const float4*)(Bb + (size_t)ldr * CC + ldk);
        As[0][ldk + 0][ldr] = a4.x; As[0][ldk + 1][ldr] = a4.y;
        As[0][ldk + 2][ldr] = a4.z; As[0][ldk + 3][ldr] = a4.w;
        Bs[0][ldk + 0][ldr] = b4.x; Bs[0][ldk + 1][ldr] = b4.y;
        Bs[0][ldk + 2][ldr] = b4.z; Bs[0][ldk + 3][ldr] = b4.w;
    }
    __syncthreads();

    int buf = 0;
    const int NK = HS / 8;  // 8
    for (int kt = 0; kt < NK; ++kt) {
        float4 a4n, b4n;
        if (kt + 1 < NK) {
            a4n = *(const float4*)(Ab + (size_t)ldr * CC + (kt + 1) * 8 + ldk);
            b4n = *(const float4*)(Bb + (size_t)ldr * CC + (kt + 1) * 8 + ldk);
        }
        mma_step(As[buf], Bs[buf], wr, wc, ar, bc, acc);
        if (kt + 1 < NK) {
            const int nb = buf ^ 1;
            As[nb][ldk + 0][ldr] = a4n.x; As[nb][ldk + 1][ldr] = a4n.y;
            As[nb][ldk + 2][ldr] = a4n.z; As[nb][ldk + 3][ldr] = a4n.w;
            Bs[nb][ldk + 0][ldr] = b4n.x; Bs[nb][ldk + 1][ldr] = b4n.y;
            Bs[nb][ldk + 2][ldr] = b4n.z; Bs[nb][ldk + 3][ldr] = b4n.w;
            __syncthreads();
            buf = nb;
        }
    }

    // epilogue: scale by 1/sqrt(64) = 0.125
#pragma unroll
    for (int i = 0; i < 8; ++i) {
        const int r = wr + ar + (i < 4 ? i : i + 12);
        float* cp = g_S + ((size_t)bh * TT + row0 + r) * TT + col0 + wc;
        *(float4*)(cp + bc) = make_float4(acc[i][0] * 0.125f, acc[i][1] * 0.125f,
                                          acc[i][2] * 0.125f, acc[i][3] * 0.125f);
        *(float4*)(cp + 32 + bc) = make_float4(acc[i][4] * 0.125f, acc[i][5] * 0.125f,
                                               acc[i][6] * 0.125f, acc[i][7] * 0.125f);
    }
}

// ---------------------------------------------------------------------------
// Kernel 2: row softmax over g_S, in place. One block per row of 2048.
// ---------------------------------------------------------------------------
__global__ __launch_bounds__(256) void softmax_kernel() {
    const size_t row = blockIdx.x;
    float* p = g_S + row * (size_t)TT;
    const int tid = threadIdx.x;
    const int warp = tid >> 5, lane = tid & 31;

    float4 v0 = *(const float4*)(p + tid * 8);
    float4 v1 = *(const float4*)(p + tid * 8 + 4);

    float m = fmaxf(fmaxf(fmaxf(v0.x, v0.y), fmaxf(v0.z, v0.w)),
                    fmaxf(fmaxf(v1.x, v1.y), fmaxf(v1.z, v1.w)));
#pragma unroll
    for (int o = 16; o; o >>= 1) m = fmaxf(m, __shfl_xor_sync(0xffffffffu, m, o));

    __shared__ float red[8];
    if (lane == 0) red[warp] = m;
    __syncthreads();
#pragma unroll
    for (int w = 0; w < 8; ++w) m = fmaxf(m, red[w]);

    v0.x = __expf(v0.x - m); v0.y = __expf(v0.y - m);
    v0.z = __expf(v0.z - m); v0.w = __expf(v0.w - m);
    v1.x = __expf(v1.x - m); v1.y = __expf(v1.y - m);
    v1.z = __expf(v1.z - m); v1.w = __expf(v1.w - m);

    float s = v0.x + v0.y + v0.z + v0.w + v1.x + v1.y + v1.z + v1.w;
#pragma unroll
    for (int o = 16; o; o >>= 1) s += __shfl_xor_sync(0xffffffffu, s, o);
    __syncthreads();  // red reuse
    if (lane == 0) red[warp] = s;
    __syncthreads();
    s = 0.f;
#pragma unroll
    for (int w = 0; w < 8; ++w) s += red[w];

    const float inv = 1.0f / s;
    v0.x *= inv; v0.y *= inv; v0.z *= inv; v0.w *= inv;
    v1.x *= inv; v1.y *= inv; v1.z *= inv; v1.w *= inv;
    *(float4*)(p + tid * 8) = v0;
    *(float4*)(p + tid * 8 + 4) = v1;
}

// ---------------------------------------------------------------------------
// Kernel 3: Z[h, r, c] = X_flat[r, :] @ W_h[:, c]   (NN GEMM, K = 1024)
// X_flat = x viewed as [B*T, C]; W_h = weight[h*C:(h+1)*C, :]
// ---------------------------------------------------------------------------
__global__ __launch_bounds__(256, 2) void z_kernel(const float* __restrict__ x,
                                                   const float* __restrict__ wt) {
    const int h    = blockIdx.z;
    const int row0 = blockIdx.y * 128;  // over B*T = 4096
    const int col0 = blockIdx.x * 128;  // over C = 1024

    const float* Ab = x + (size_t)row0 * CC;
    const float* Bb = wt + (size_t)h * CC * CC + col0;
    float* Cb = g_Z + (size_t)h * (BB * TT) * CC + (size_t)row0 * CC + col0;

    __shared__ float As[2][8][128];
    __shared__ float Bs[2][8][128];

    const int tid  = threadIdx.x;
    const int ldr  = tid >> 1;
    const int ldk  = (tid & 1) * 4;
    const int brow = tid >> 5;              // 0..7
    const int bcol = (tid & 31) * 4;        // 0..124
    const int warp = tid >> 5, lane = tid & 31;
    const int wr = (warp & 3) * 32, wc = (warp >> 2) * 64;
    const int ar = (lane >> 3) * 4, bc = (lane & 7) * 4;

    float acc[8][8];
#pragma unroll
    for (int i = 0; i < 8; ++i)
#pragma unroll
        for (int j = 0; j < 8; ++j) acc[i][j] = 0.f;

    {
        float4 a4 = *(const float4*)(Ab + (size_t)ldr * CC + ldk);
        float4 b4 = *(const float4*)(Bb + (size_t)brow * CC + bcol);
        As[0][ldk + 0][ldr] = a4.x; As[0][ldk + 1][ldr] = a4.y;
        As[0][ldk + 2][ldr] = a4.z; As[0][ldk + 3][ldr] = a4.w;
        *(float4*)&Bs[0][brow][bcol] = b4;
    }
    __syncthreads();

    int buf = 0;
    const int NK = CC / 8;  // 128
    for (int kt = 0; kt < NK; ++kt) {
        float4 a4n, b4n;
        if (kt + 1 < NK) {
            a4n = *(const float4*)(Ab + (size_t)ldr * CC + (kt + 1) * 8 + ldk);
            b4n = *(const float4*)(Bb + (size_t)((kt + 1) * 8 + brow) * CC + bcol);
        }
        mma_step(As[buf], Bs[buf], wr, wc, ar, bc, acc);
        if (kt + 1 < NK) {
            const int nb = buf ^ 1;
            As[nb][ldk + 0][ldr] = a4n.x; As[nb][ldk + 1][ldr] = a4n.y;
            As[nb][ldk + 2][ldr] = a4n.z; As[nb][ldk + 3][ldr] = a4n.w;
            *(float4*)&Bs[nb][brow][bcol] = b4n;
            __syncthreads();
            buf = nb;
        }
    }

#pragma unroll
    for (int i = 0; i < 8; ++i) {
        const int r = wr + ar + (i < 4 ? i : i + 12);
        float* cp = Cb + (size_t)r * CC + wc;
        *(float4*)(cp + bc) = make_float4(acc[i][0], acc[i][1], acc[i][2], acc[i][3]);
        *(float4*)(cp + 32 + bc) = make_float4(acc[i][4], acc[i][5], acc[i][6], acc[i][7]);
    }
}

// ---------------------------------------------------------------------------
// Kernel 4: out[b, t, c] = sum_h sum_s P[b,h,t,s] * Z[h, b*T+s, c]
// One GEMM per b with K = NH*T = 32768 (h outer, s inner).
// ---------------------------------------------------------------------------
__global__ __launch_bounds__(256, 2) void out_kernel(float* __restrict__ out) {
    const int b    = blockIdx.z;
    const int row0 = blockIdx.y * 128;  // t tile
    const int col0 = blockIdx.x * 128;  // c tile

    __shared__ float As[2][8][128];
    __shared__ float Bs[2][8][128];

    const int tid  = threadIdx.x;
    const int ldr  = tid >> 1;
    const int ldk  = (tid & 1) * 4;
    const int brow = tid >> 5;
    const int bcol = (tid & 31) * 4;
    const int warp = tid >> 5, lane = tid & 31;
    const int wr = (warp & 3) * 32, wc = (warp >> 2) * 64;
    const int ar = (lane >> 3) * 4, bc = (lane & 7) * 4;

    float acc[8][8];
#pragma unroll
    for (int i = 0; i < 8; ++i)
#pragma unroll
        for (int j = 0; j < 8; ++j) acc[i][j] = 0.f;

    // k-tile pointer helpers: kk = kt*8 ; h = kk>>11 ; s = kk & 2047
    {
        const float* Ap = g_S + ((size_t)((b * NH + 0) * TT) + row0 + ldr) * TT + 0 + ldk;
        const float* Bp = g_Z + ((size_t)((0 * BB + b) * TT) + 0 + brow) * CC + col0 + bcol;
        float4 a4 = *(const float4*)Ap;
        float4 b4 = *(const float4*)Bp;
        As[0][ldk + 0][ldr] = a4.x; As[0][ldk + 1][ldr] = a4.y;
        As[0][ldk + 2][ldr] = a4.z; As[0][ldk + 3][ldr] = a4.w;
        *(float4*)&Bs[0][brow][bcol] = b4;
    }
    __syncthreads();

    int buf = 0;
    const int NK = (NH * TT) / 8;  // 4096
    for (int kt = 0; kt < NK; ++kt) {
        float4 a4n, b4n;
        if (kt + 1 < NK) {
            const int kk = (kt + 1) * 8;
            const int h = kk >> 11;
            const int s = kk & 2047;
            const float* Ap = g_S + ((size_t)((b * NH + h) * TT) + row0 + ldr) * TT + s + ldk;
            const float* Bp = g_Z + ((size_t)((h * BB + b) * TT) + s + brow) * CC + col0 + bcol;
            a4n = *(const float4*)Ap;
            b4n = *(const float4*)Bp;
        }
        mma_step(As[buf], Bs[buf], wr, wc, ar, bc, acc);
        if (kt + 1 < NK) {
            const int nb = buf ^ 1;
            As[nb][ldk + 0][ldr] = a4n.x; As[nb][ldk + 1][ldr] = a4n.y;
            As[nb][ldk + 2][ldr] = a4n.z; As[nb][ldk + 3][ldr] = a4n.w;
            *(float4*)&Bs[nb][brow][bcol] = b4n;
            __syncthreads();
            buf = nb;
        }
    }

#pragma unroll
    for (int i = 0; i < 8; ++i) {
        const int r = wr + ar + (i < 4 ? i : i + 12);
        float* cp = out + ((size_t)(b * TT + row0 + r)) * CC + col0 + wc;
        *(float4*)(cp + bc) = make_float4(acc[i][0], acc[i][1], acc[i][2], acc[i][3]);
        *(float4*)(cp + 32 + bc) = make_float4(acc[i][4], acc[i][5], acc[i][6], acc[i][7]);
    }
}

// ---------------------------------------------------------------------------
extern "C" void kernel_launch(void* const* d_in, const int* in_sizes, int n_in,
                              void* d_out, int out_size) {
    const float* x  = (const float*)d_in[0];   // [2, 2048, 1024]
    const float* wt = (const float*)d_in[1];   // [16384, 1024]
    float* out = (float*)d_out;                // [2, 2048, 1024]

    scores_kernel<<<dim3(TT / 128, TT / 128, BB * NH), 256>>>(x);
    softmax_kernel<<<BB * NH * TT, 256>>>();
    z_kernel<<<dim3(CC / 128, (BB * TT) / 128, NH), 256>>>(x, wt);
    out_kernel<<<dim3(CC / 128, TT / 128, BB), 256>>>(out);
}

// round 5
// speedup vs baseline: 3.3957x; 3.3957x over previous
#include <cuda_runtime.h>
#include <cuda_bf16.h>
#include <cstdint>

#define TSEQ 2048
#define CEMB 1024

// ---------------- scratch (__device__ globals; no allocations) ----------------
__device__ __align__(128) float         g_S[134217728];     // [2,16,2048,2048] fp32
__device__ __align__(128) __nv_bfloat16 g_Phi[134217728];   // probs hi
__device__ __align__(128) __nv_bfloat16 g_Plo[134217728];   // probs lo
__device__ __align__(128) __nv_bfloat16 g_xhi[4194304];     // [4096,1024]
__device__ __align__(128) __nv_bfloat16 g_xlo[4194304];
__device__ __align__(128) __nv_bfloat16 g_wthi[16777216];   // Wt[h][n][k]
__device__ __align__(128) __nv_bfloat16 g_wtlo[16777216];
__device__ __align__(128) __nv_bfloat16 g_Zhi[67108864];    // [16][4096 r][1024 c]
__device__ __align__(128) __nv_bfloat16 g_Zlo[67108864];

// ---------------- low-level helpers ----------------
__device__ __forceinline__ uint32_t smem_u32(const void* p) {
    uint32_t a;
    asm("{ .reg .u64 t; cvta.to.shared.u64 t, %1; cvt.u32.u64 %0, t; }" : "=r"(a) : "l"(p));
    return a;
}
__device__ __forceinline__ void cp16(uint32_t dst, const void* src) {
    asm volatile("cp.async.cg.shared.global [%0], [%1], 16;" :: "r"(dst), "l"(src));
}
__device__ __forceinline__ void cp_commit() { asm volatile("cp.async.commit_group;" ::: "memory"); }
template <int N> __device__ __forceinline__ void cp_wait() {
    asm volatile("cp.async.wait_group %0;" :: "n"(N) : "memory");
}
__device__ __forceinline__ void ldmx4(uint32_t r[4], uint32_t a) {
    asm volatile("ldmatrix.sync.aligned.m8n8.x4.shared.b16 {%0,%1,%2,%3}, [%4];"
                 : "=r"(r[0]), "=r"(r[1]), "=r"(r[2]), "=r"(r[3]) : "r"(a));
}
__device__ __forceinline__ void ldmx4t(uint32_t r[4], uint32_t a) {
    asm volatile("ldmatrix.sync.aligned.m8n8.x4.trans.shared.b16 {%0,%1,%2,%3}, [%4];"
                 : "=r"(r[0]), "=r"(r[1]), "=r"(r[2]), "=r"(r[3]) : "r"(a));
}
__device__ __forceinline__ void mma16816(float* c, const uint32_t* a, const uint32_t* b) {
    asm volatile(
        "mma.sync.aligned.m16n8k16.row.col.f32.bf16.bf16.f32 "
        "{%0,%1,%2,%3}, {%4,%5,%6,%7}, {%8,%9}, {%0,%1,%2,%3};"
        : "+f"(c[0]), "+f"(c[1]), "+f"(c[2]), "+f"(c[3])
        : "r"(a[0]), "r"(a[1]), "r"(a[2]), "r"(a[3]), "r"(b[0]), "r"(b[1]));
}
__device__ __forceinline__ void split_bf16(float v, __nv_bfloat16& hi, __nv_bfloat16& lo) {
    hi = __float2bfloat16(v);
    lo = __float2bfloat16(v - __bfloat162float(hi));
}
__device__ __forceinline__ uint32_t pack2(__nv_bfloat16 a, __nv_bfloat16 b) {
    union { __nv_bfloat16 h[2]; uint32_t u; } v; v.h[0] = a; v.h[1] = b; return v.u;
}

// ---------------- smem stage layout ----------------
// A(hi) 128x32 @ pitch 80B : 10240 B @ +0     ; A(lo) @ +10240
// B(hi): K-major 128x32 @ pitch 80B (10240 B) OR S-major 32x128 @ pitch 272B (8704 B) @ +20480
// B(lo) @ +30720
#define STAGE 40960u
#define SMEM_SC  (2 * STAGE)
#define SMEM_P3  (3 * STAGE)

__device__ __forceinline__ void copyA(uint32_t sb, const __nv_bfloat16* hi,
                                      const __nv_bfloat16* lo, int ld, int tid) {
#pragma unroll
    for (int i = 0; i < 2; ++i) {               // 512 chunks: 128 rows x 4 x 16B
        const int idx = tid + i * 256;
        const int r = idx >> 2, c = idx & 3;
        const uint32_t d = sb + (uint32_t)r * 80u + (uint32_t)c * 16u;
        const size_t g = (size_t)r * ld + c * 8;
        cp16(d, hi + g);
        cp16(d + 10240u, lo + g);
    }
}
__device__ __forceinline__ void copyBK(uint32_t sb, const __nv_bfloat16* hi,
                                       const __nv_bfloat16* lo, int ld, int tid) {
#pragma unroll
    for (int i = 0; i < 2; ++i) {               // 512 chunks: 128 rows x 4 x 16B
        const int idx = tid + i * 256;
        const int r = idx >> 2, c = idx & 3;
        const uint32_t d = sb + 20480u + (uint32_t)r * 80u + (uint32_t)c * 16u;
        const size_t g = (size_t)r * ld + c * 8;
        cp16(d, hi + g);
        cp16(d + 10240u, lo + g);
    }
}
// FIXED: full 32 rows x 128 cols = 512 chunks (was 256 -> half tile uninitialized -> NaN)
__device__ __forceinline__ void copyBS(uint32_t sb, const __nv_bfloat16* hi,
                                       const __nv_bfloat16* lo, int ld, int tid) {
#pragma unroll
    for (int i = 0; i < 2; ++i) {               // 512 chunks: 32 rows x 16 x 16B
        const int idx = tid + i * 256;
        const int r = idx >> 4, c = idx & 15;
        const uint32_t d = sb + 20480u + (uint32_t)r * 272u + (uint32_t)c * 16u;
        const size_t g = (size_t)r * ld + c * 8;
        cp16(d, hi + g);
        cp16(d + 10240u, lo + g);
    }
}

// ---------------- warp-tile compute: 32x64 per warp, 3-product split ----------------
template <int BSMAJ>
__device__ __forceinline__ void compute_stage(uint32_t sb, int wm, int wn, int lane,
                                              float (&acc)[2][8][4]) {
#pragma unroll
    for (int ks = 0; ks < 2; ++ks) {
        const int k0 = ks * 16;
        uint32_t Ah[2][4], Al[2][4], Bh[4][4], Bl[4][4];
#pragma unroll
        for (int mt = 0; mt < 2; ++mt) {
            const uint32_t ad = sb + (uint32_t)(wm + mt * 16 + (lane & 15)) * 80u +
                                (uint32_t)(k0 + (lane >> 4) * 8) * 2u;
            ldmx4(Ah[mt], ad);
            ldmx4(Al[mt], ad + 10240u);
        }
#pragma unroll
        for (int np = 0; np < 4; ++np) {
            if (BSMAJ) {
                const uint32_t ad = sb + 20480u +
                    (uint32_t)(k0 + (lane & 7) + ((lane >> 3) & 1) * 8) * 272u +
                    (uint32_t)(wn + np * 16 + (lane >> 4) * 8) * 2u;
                ldmx4t(Bh[np], ad);
                ldmx4t(Bl[np], ad + 10240u);
            } else {
                const uint32_t ad = sb + 20480u +
                    (uint32_t)(wn + np * 16 + (lane & 7) + (lane >> 4) * 8) * 80u +
                    (uint32_t)(k0 + ((lane >> 3) & 1) * 8) * 2u;
                ldmx4(Bh[np], ad);
                ldmx4(Bl[np], ad + 10240u);
            }
        }
#pragma unroll
        for (int mt = 0; mt < 2; ++mt)
#pragma unroll
            for (int nt = 0; nt < 8; ++nt) {
                const uint32_t* bh = &Bh[nt >> 1][(nt & 1) * 2];
                const uint32_t* bl = &Bl[nt >> 1][(nt & 1) * 2];
                mma16816(acc[mt][nt], Ah[mt], bh);
                mma16816(acc[mt][nt], Ah[mt], bl);
                mma16816(acc[mt][nt], Al[mt], bh);
            }
    }
}

#define GEMM_PRE()                                                  \
    extern __shared__ char smraw[];                                 \
    const uint32_t sb = smem_u32(smraw);                            \
    const int tid = threadIdx.x, lane = tid & 31, warp = tid >> 5;  \
    const int wm = (warp & 3) * 32, wn = (warp >> 2) * 64;          \
    float acc[2][8][4];                                             \
    _Pragma("unroll") for (int i = 0; i < 2; ++i)                   \
    _Pragma("unroll") for (int j = 0; j < 8; ++j)                   \
    _Pragma("unroll") for (int q = 0; q < 4; ++q) acc[i][j][q] = 0.f;

// ---------------- aux kernels ----------------
__global__ __launch_bounds__(256) void xsplit_kernel(const float* __restrict__ x) {
    const size_t i = (size_t)blockIdx.x * 256 + threadIdx.x;
    float4 v = *(const float4*)(x + i * 4);
    union { __nv_bfloat16 a[4]; uint2 u; } H, L;
    split_bf16(v.x, H.a[0], L.a[0]); split_bf16(v.y, H.a[1], L.a[1]);
    split_bf16(v.z, H.a[2], L.a[2]); split_bf16(v.w, H.a[3], L.a[3]);
    *(uint2*)(g_xhi + i * 4) = H.u;
    *(uint2*)(g_xlo + i * 4) = L.u;
}

__global__ __launch_bounds__(256) void wsplit_kernel(const float* __restrict__ wt) {
    __shared__ float tile[32][33];
    const int h = blockIdx.z, k0 = blockIdx.y * 32, n0 = blockIdx.x * 32;
    const int tx = threadIdx.x, ty = threadIdx.y;
#pragma unroll
    for (int j = 0; j < 4; ++j)
        tile[ty + 8 * j][tx] = wt[((size_t)h * 1024 + k0 + ty + 8 * j) * 1024 + n0 + tx];
    __syncthreads();
#pragma unroll
    for (int j = 0; j < 4; ++j) {
        const int nn = ty + 8 * j, kk = tx;
        __nv_bfloat16 hi, lo; split_bf16(tile[kk][nn], hi, lo);
        const size_t o = ((size_t)h * 1024 + n0 + nn) * 1024 + k0 + kk;
        g_wthi[o] = hi; g_wtlo[o] = lo;
    }
}

__global__ __launch_bounds__(256) void softmax_kernel() {
    const size_t row = blockIdx.x;
    float* p = g_S + row * (size_t)TSEQ;
    const int tid = threadIdx.x, warp = tid >> 5, lane = tid & 31;

    float4 v0 = *(const float4*)(p + tid * 8);
    float4 v1 = *(const float4*)(p + tid * 8 + 4);
    float m = fmaxf(fmaxf(fmaxf(v0.x, v0.y), fmaxf(v0.z, v0.w)),
                    fmaxf(fmaxf(v1.x, v1.y), fmaxf(v1.z, v1.w)));
#pragma unroll
    for (int o = 16; o; o >>= 1) m = fmaxf(m, __shfl_xor_sync(0xffffffffu, m, o));
    __shared__ float red[8];
    if (lane == 0) red[warp] = m;
    __syncthreads();
#pragma unroll
    for (int w = 0; w < 8; ++w) m = fmaxf(m, red[w]);

    v0.x = __expf(v0.x - m); v0.y = __expf(v0.y - m);
    v0.z = __expf(v0.z - m); v0.w = __expf(v0.w - m);
    v1.x = __expf(v1.x - m); v1.y = __expf(v1.y - m);
    v1.z = __expf(v1.z - m); v1.w = __expf(v1.w - m);
    float s = v0.x + v0.y + v0.z + v0.w + v1.x + v1.y + v1.z + v1.w;
#pragma unroll
    for (int o = 16; o; o >>= 1) s += __shfl_xor_sync(0xffffffffu, s, o);
    __syncthreads();
    if (lane == 0) red[warp] = s;
    __syncthreads();
    s = 0.f;
#pragma unroll
    for (int w = 0; w < 8; ++w) s += red[w];
    const float inv = 1.0f / s;

    float vals[8] = {v0.x * inv, v0.y * inv, v0.z * inv, v0.w * inv,
                     v1.x * inv, v1.y * inv, v1.z * inv, v1.w * inv};
    union { __nv_bfloat16 a[8]; uint4 u; } H, L;
#pragma unroll
    for (int k = 0; k < 8; ++k) split_bf16(vals[k], H.a[k], L.a[k]);
    *(uint4*)(g_Phi + row * TSEQ + tid * 8) = H.u;
    *(uint4*)(g_Plo + row * TSEQ + tid * 8) = L.u;
}

// ---------------- scores: S = y.yT / 8  (128x128 tiles, K=64) ----------------
__global__ __launch_bounds__(256, 1) void scores_hmma() {
    GEMM_PRE();
    const int bh = blockIdx.z, b = bh >> 4, hh = bh & 15;
    const int row0 = blockIdx.y * 128, col0 = blockIdx.x * 128;

    const size_t ab = (size_t)(b * TSEQ + row0) * CEMB + hh * 64;
    const size_t bb = (size_t)(b * TSEQ + col0) * CEMB + hh * 64;

    copyA(sb, g_xhi + ab, g_xlo + ab, CEMB, tid);
    copyBK(sb, g_xhi + bb, g_xlo + bb, CEMB, tid);
    cp_commit();
#pragma unroll
    for (int kt = 0; kt < 2; ++kt) {
        if (kt == 0) {
            copyA(sb + STAGE, g_xhi + ab + 32, g_xlo + ab + 32, CEMB, tid);
            copyBK(sb + STAGE, g_xhi + bb + 32, g_xlo + bb + 32, CEMB, tid);
            cp_commit();
            cp_wait<1>();
        } else cp_wait<0>();
        __syncthreads();
        compute_stage<0>(sb + kt * STAGE, wm, wn, lane, acc);
        __syncthreads();
    }

    const int g = lane >> 2, t2 = (lane & 3) * 2;
    float* Sp = g_S + ((size_t)bh * TSEQ + row0) * TSEQ + col0;
#pragma unroll
    for (int mt = 0; mt < 2; ++mt)
#pragma unroll
        for (int nt = 0; nt < 8; ++nt) {
            const int r = wm + mt * 16 + g, c = wn + nt * 8 + t2;
            *(float2*)(Sp + (size_t)r * TSEQ + c) =
                make_float2(acc[mt][nt][0] * 0.125f, acc[mt][nt][1] * 0.125f);
            *(float2*)(Sp + (size_t)(r + 8) * TSEQ + c) =
                make_float2(acc[mt][nt][2] * 0.125f, acc[mt][nt][3] * 0.125f);
        }
}

// ---------------- Z[h] = X @ W_h (K=1024), writes bf16 hi/lo, 3-stage ----------------
__global__ __launch_bounds__(256, 1) void z_hmma() {
    GEMM_PRE();
    const int hh = blockIdx.z;
    const int row0 = blockIdx.y * 128, col0 = blockIdx.x * 128;

    const size_t ab = (size_t)row0 * CEMB;
    const size_t bb = ((size_t)hh * 1024 + col0) * 1024;

    auto loadT = [&](int t) {
        const uint32_t st = sb + (uint32_t)(t % 3) * STAGE;
        copyA(st, g_xhi + ab + t * 32, g_xlo + ab + t * 32, CEMB, tid);
        copyBK(st, g_wthi + bb + t * 32, g_wtlo + bb + t * 32, 1024, tid);
    };
    loadT(0); cp_commit();
    loadT(1); cp_commit();
    const int NK = 32;
    for (int kt = 0; kt < NK; ++kt) {
        if (kt + 2 < NK) loadT(kt + 2);
        cp_commit();                 // empty groups keep wait-window exact at the tail
        cp_wait<2>();
        __syncthreads();
        compute_stage<0>(sb + (uint32_t)(kt % 3) * STAGE, wm, wn, lane, acc);
        __syncthreads();
    }

    const int g = lane >> 2, t2 = (lane & 3) * 2;
#pragma unroll
    for (int mt = 0; mt < 2; ++mt)
#pragma unroll
        for (int nt = 0; nt < 8; ++nt) {
            const int r = row0 + wm + mt * 16 + g;
            const int c = col0 + wn + nt * 8 + t2;
            __nv_bfloat16 h0, l0, h1, l1, h2, l2, h3, l3;
            split_bf16(acc[mt][nt][0], h0, l0);
            split_bf16(acc[mt][nt][1], h1, l1);
            split_bf16(acc[mt][nt][2], h2, l2);
            split_bf16(acc[mt][nt][3], h3, l3);
            const size_t o0 = ((size_t)hh * 4096 + r) * 1024 + c;
            *(uint32_t*)(g_Zhi + o0) = pack2(h0, h1);
            *(uint32_t*)(g_Zlo + o0) = pack2(l0, l1);
            const size_t o1 = o0 + 8 * 1024;
            *(uint32_t*)(g_Zhi + o1) = pack2(h2, h3);
            *(uint32_t*)(g_Zlo + o1) = pack2(l2, l3);
        }
}

// ---------------- out[b] = sum_h P[b,h] @ Z[h,b]  (K = 32768), 3-stage ----------------
__global__ __launch_bounds__(256, 1) void out_hmma(float* __restrict__ out) {
    GEMM_PRE();
    const int b = blockIdx.z;
    const int row0 = blockIdx.y * 128, col0 = blockIdx.x * 128;

    const size_t arow = ((size_t)(b * 16) * TSEQ + row0) * TSEQ;
    auto loadT = [&](int t) {                    // t: hh = t>>6, s0 = (t&63)*32
        const int hh = t >> 6, s0 = (t & 63) * 32;
        const size_t ab = arow + (size_t)hh * TSEQ * TSEQ + s0;
        const size_t bb = ((size_t)hh * 4096 + b * TSEQ + s0) * 1024 + col0;
        const uint32_t st = sb + (uint32_t)(t % 3) * STAGE;
        copyA(st, g_Phi + ab, g_Plo + ab, TSEQ, tid);
        copyBS(st, g_Zhi + bb, g_Zlo + bb, 1024, tid);
    };
    loadT(0); cp_commit();
    loadT(1); cp_commit();
    const int NK = 1024;
    for (int kt = 0; kt < NK; ++kt) {
        if (kt + 2 < NK) loadT(kt + 2);
        cp_commit();
        cp_wait<2>();
        __syncthreads();
        compute_stage<1>(sb + (uint32_t)(kt % 3) * STAGE, wm, wn, lane, acc);
        __syncthreads();
    }

    const int g = lane >> 2, t2 = (lane & 3) * 2;
    float* Op = out + ((size_t)(b * TSEQ + row0)) * CEMB + col0;
#pragma unroll
    for (int mt = 0; mt < 2; ++mt)
#pragma unroll
        for (int nt = 0; nt < 8; ++nt) {
            const int r = wm + mt * 16 + g, c = wn + nt * 8 + t2;
            *(float2*)(Op + (size_t)r * CEMB + c) = make_float2(acc[mt][nt][0], acc[mt][nt][1]);
            *(float2*)(Op + (size_t)(r + 8) * CEMB + c) = make_float2(acc[mt][nt][2], acc[mt][nt][3]);
        }
}

// ---------------------------------------------------------------------------
extern "C" void kernel_launch(void* const* d_in, const int* in_sizes, int n_in,
                              void* d_out, int out_size) {
    const float* x  = (const float*)d_in[0];   // [2,2048,1024]
    const float* wt = (const float*)d_in[1];   // [16384,1024]
    float* out = (float*)d_out;

    cudaFuncSetAttribute(scores_hmma, cudaFuncAttributeMaxDynamicSharedMemorySize, SMEM_SC);
    cudaFuncSetAttribute(z_hmma,      cudaFuncAttributeMaxDynamicSharedMemorySize, SMEM_P3);
    cudaFuncSetAttribute(out_hmma,    cudaFuncAttributeMaxDynamicSharedMemorySize, SMEM_P3);

    xsplit_kernel<<<4096, 256>>>(x);
    wsplit_kernel<<<dim3(32, 32, 16), dim3(32, 8)>>>(wt);
    scores_hmma<<<dim3(16, 16, 32), 256, SMEM_SC>>>();
    softmax_kernel<<<65536, 256>>>();
    z_hmma<<<dim3(8, 32, 16), 256, SMEM_P3>>>();
    out_hmma<<<dim3(8, 16, 2), 256, SMEM_P3>>>(out);
}